// round 7
// baseline (speedup 1.0000x reference)
#include <cuda_runtime.h>
#include <cuda_bf16.h>
#include <cstdint>

#define NB 4
#define NC 128
#define NH 256
#define NW 512
#define ND 64
#define W_TILE 64
#define THREADS 256

// SMEM (bytes): bf16 tiles, rows of 128 k-elements = 256B (16 chunks of 16B).
// Chunk-XOR swizzle: chunk' = chunk ^ (row & 7) -> ldmatrix conflict-free.
#define SM_AHI  0                       // A_hi [128m x 128k] bf16 (32KB)
#define SM_ALO  (SM_AHI + 32768)        // A_lo (32KB)
#define SM_BHI  (SM_ALO + 32768)        // B_hi [64n x 128k] bf16 (16KB)
#define SM_BLO  (SM_BHI + 16384)        // B_lo (16KB)
#define SMEM_TOTAL (SM_BLO + 16384)     // 98304 -> 2 CTAs/SM

__device__ __forceinline__ uint32_t smem_u32(const void* p) {
    uint32_t a;
    asm("{ .reg .u64 t; cvta.to.shared.u64 t, %1; cvt.u32.u64 %0, t; }" : "=r"(a) : "l"(p));
    return a;
}
__device__ __forceinline__ uint32_t tile_off(int row, int k) {
    return (uint32_t)(row * 256 + (((k >> 3) ^ (row & 7)) << 4) + (k & 7) * 2);
}
__device__ __forceinline__ void bsplit(float x, uint16_t& hi, uint16_t& lo) {
    __nv_bfloat16 h = __float2bfloat16(x);
    __nv_bfloat16 l = __float2bfloat16(x - __bfloat162float(h));
    hi = *reinterpret_cast<uint16_t*>(&h);
    lo = *reinterpret_cast<uint16_t*>(&l);
}
// Packed split of 2 floats -> (hi bf16x2, lo bf16x2)
__device__ __forceinline__ void bsplit2(float x, float y, uint32_t& hi, uint32_t& lo) {
    __nv_bfloat162 h2 = __floats2bfloat162_rn(x, y);   // low half = x
    uint32_t u = *reinterpret_cast<uint32_t*>(&h2);
    float hx = __uint_as_float(u << 16);
    float hy = __uint_as_float(u & 0xFFFF0000u);
    __nv_bfloat162 l2 = __floats2bfloat162_rn(x - hx, y - hy);
    hi = u;
    lo = *reinterpret_cast<uint32_t*>(&l2);
}
__device__ __forceinline__ void ldsm4(uint32_t* r, uint32_t addr) {
    asm volatile("ldmatrix.sync.aligned.m8n8.x4.shared.b16 {%0,%1,%2,%3}, [%4];"
                 : "=r"(r[0]), "=r"(r[1]), "=r"(r[2]), "=r"(r[3]) : "r"(addr));
}
__device__ __forceinline__ void mma16816(float* c, const uint32_t* a, const uint32_t* b) {
    asm volatile("mma.sync.aligned.m16n8k16.row.col.f32.bf16.bf16.f32 "
                 "{%0,%1,%2,%3}, {%4,%5,%6,%7}, {%8,%9}, {%0,%1,%2,%3};"
                 : "+f"(c[0]), "+f"(c[1]), "+f"(c[2]), "+f"(c[3])
                 : "r"(a[0]), "r"(a[1]), "r"(a[2]), "r"(a[3]), "r"(b[0]), "r"(b[1]));
}

// Band-pruned mainloop, specialized on the warp's n offset (0 or 32).
// B[w][k] nonzero iff k-w in [0,64). For n8 tile at nb: nonzero k in [nb, nb+70].
template <int NWARP>
__device__ __forceinline__ void mainloop(uint32_t smb, int m_warp,
                                         int a_m, int a_ks, int b_n, int b_ks,
                                         float acc[2][4][4])
{
    #pragma unroll
    for (int ks = 0; ks < 8; ks++) {
        const bool needA = (ks >= NWARP / 16) && (ks <= NWARP / 16 + 5);
        if (!needA) continue;
        uint32_t ahi[2][4], alo[2][4], bhi[2][4], blo[2][4];
        #pragma unroll
        for (int mt = 0; mt < 2; mt++) {
            const int m = m_warp + mt * 16 + a_m;
            const uint32_t off = (uint32_t)(m * 256 + (((ks * 2 + a_ks) ^ (m & 7)) << 4));
            ldsm4(ahi[mt], smb + SM_AHI + off);
            ldsm4(alo[mt], smb + SM_ALO + off);
        }
        #pragma unroll
        for (int p = 0; p < 2; p++) {
            const bool needB = (ks >= NWARP / 16 + p) && (ks <= NWARP / 16 + p + 4);
            if (!needB) continue;
            const int n = NWARP + p * 16 + b_n;
            const uint32_t off = (uint32_t)(n * 256 + (((ks * 2 + b_ks) ^ (n & 7)) << 4));
            ldsm4(bhi[p], smb + SM_BHI + off);
            ldsm4(blo[p], smb + SM_BLO + off);
        }
        #pragma unroll
        for (int mt = 0; mt < 2; mt++) {
            #pragma unroll
            for (int nt = 0; nt < 4; nt++) {
                const int nb = NWARP + nt * 8;
                const bool use = (16 * ks <= nb + 70) && (16 * ks + 15 >= nb);
                if (!use) continue;
                const uint32_t* bh = &bhi[nt >> 1][(nt & 1) * 2];
                const uint32_t* bl = &blo[nt >> 1][(nt & 1) * 2];
                mma16816(acc[mt][nt], ahi[mt], bh);
                mma16816(acc[mt][nt], ahi[mt], bl);
                mma16816(acc[mt][nt], alo[mt], bh);
            }
        }
    }
}

__global__ void __launch_bounds__(THREADS, 2)
corr_mma_kernel(const float* __restrict__ h1,
                const float* __restrict__ cost,
                float* __restrict__ out)
{
    extern __shared__ char smem[];
    const uint32_t smb = smem_u32(smem);
    const int tid  = threadIdx.x;
    const int wid  = tid >> 5;
    const int lane = tid & 31;

    const int wt = blockIdx.x;   // 0..7
    const int hh = blockIdx.y;   // 0..255
    const int bb = blockIdx.z;   // 0..3
    const int w0 = wt * W_TILE;

    // ---- Phase 1a: cost LDG first (latency overlaps A conversion) ----
    float4 cv[4];
    int cd[4], cw[4];
    #pragma unroll
    for (int j = 0; j < 4; j++) {
        const int idx = j * THREADS + tid;
        cd[j] = idx >> 4;          // d
        cw[j] = (idx & 15) * 4;    // w base
        cv[j] = *reinterpret_cast<const float4*>(
                    cost + (((size_t)bb * ND + cd[j]) * NH + hh) * NW + w0 + cw[j]);
    }

    // ---- Phase 1b: sparse-zero B. Row w is only read in k in [16*(w/16), +80);
    // outside the band that leaves stripes k in [16m0,16m0+16) u [16m0+64,+80).
    // 64 rows x 4 chunks x 2 tiles = 512 16B chunk-zeros -> 2 per thread.
    {
        const uint4 z = make_uint4(0, 0, 0, 0);
        #pragma unroll
        for (int i = 0; i < 2; i++) {
            const int idx  = tid * 2 + i;        // 0..511
            const int tile = idx >> 8;           // 0 = hi, 1 = lo
            const int rr   = idx & 255;
            const int row  = rr >> 2;            // 0..63
            const int cc   = rr & 3;
            const int chunk = 2 * (row >> 4) + (cc & 1) + (cc >> 1) * 8;
            const uint32_t off = tile_off(row, chunk * 8);
            *reinterpret_cast<uint4*>(smem + (tile ? SM_BLO : SM_BHI) + off) = z;
        }
    }

    // ---- Phase 1c: load+split A. Thread handles 8 consecutive k -> 16B STS hi+lo ----
    {
        #pragma unroll
        for (int j = 0; j < 8; j++) {
            const int idx = j * THREADS + tid;   // 0..2047
            const int row = idx >> 4;            // c 0..127
            const int q8  = idx & 15;            // 8-elem group
            const int gw  = w0 + q8 * 8;
            uint4 hp = make_uint4(0, 0, 0, 0), lp = make_uint4(0, 0, 0, 0);
            if (gw < NW) {
                const float* src = h1 + (((size_t)bb * NC + row) * NH + hh) * NW + gw;
                const float4 v0 = *reinterpret_cast<const float4*>(src);
                const float4 v1 = *reinterpret_cast<const float4*>(src + 4);
                bsplit2(v0.x, v0.y, hp.x, lp.x);
                bsplit2(v0.z, v0.w, hp.y, lp.y);
                bsplit2(v1.x, v1.y, hp.z, lp.z);
                bsplit2(v1.z, v1.w, hp.w, lp.w);
            }
            const uint32_t off = tile_off(row, q8 * 8);   // 16B aligned
            *reinterpret_cast<uint4*>(smem + SM_AHI + off) = hp;
            *reinterpret_cast<uint4*>(smem + SM_ALO + off) = lp;
        }
    }
    __syncthreads();

    // ---- Phase 2: shear-scatter cost into B: B[w][w+d] = cost[d][w] ----
    {
        #pragma unroll
        for (int j = 0; j < 4; j++) {
            const float x[4] = {cv[j].x, cv[j].y, cv[j].z, cv[j].w};
            #pragma unroll
            for (int e = 0; e < 4; e++) {
                const int w = cw[j] + e;
                const uint32_t off = tile_off(w, w + cd[j]);
                uint16_t hi, lo;
                bsplit(x[e], hi, lo);
                *reinterpret_cast<uint16_t*>(smem + SM_BHI + off) = hi;
                *reinterpret_cast<uint16_t*>(smem + SM_BLO + off) = lo;
            }
        }
    }
    __syncthreads();

    // ---- Phase 3: warp-tile GEMM. Warp = 32m x 32n; band-pruned K ----
    const int m_warp = (wid & 3) * 32;
    const int n_warp = (wid >> 2) * 32;
    const int qd = lane >> 2;
    const int tq = lane & 3;

    const int sub  = lane >> 3;
    const int rid  = lane & 7;
    const int a_m  = (sub & 1) * 8 + rid;
    const int a_ks = (sub >> 1);
    const int b_n  = (sub >> 1) * 8 + rid;
    const int b_ks = (sub & 1);

    float acc[2][4][4];
    #pragma unroll
    for (int mt = 0; mt < 2; mt++)
        #pragma unroll
        for (int nt = 0; nt < 4; nt++)
            #pragma unroll
            for (int e = 0; e < 4; e++) acc[mt][nt][e] = 0.f;

    if (n_warp == 0)
        mainloop<0>(smb, m_warp, a_m, a_ks, b_n, b_ks, acc);
    else
        mainloop<32>(smb, m_warp, a_m, a_ks, b_n, b_ks, acc);

    // ---- Epilogue ----
    {
        #pragma unroll
        for (int mt = 0; mt < 2; mt++) {
            const int m0 = m_warp + mt * 16 + qd;
            float* r0 = out + (((size_t)bb * NC + m0) * NH + hh) * NW + w0 + n_warp;
            float* r1 = out + (((size_t)bb * NC + m0 + 8) * NH + hh) * NW + w0 + n_warp;
            #pragma unroll
            for (int nt = 0; nt < 4; nt++) {
                const int nc2 = nt * 8 + tq * 2;
                *reinterpret_cast<float2*>(r0 + nc2) = make_float2(acc[mt][nt][0], acc[mt][nt][1]);
                *reinterpret_cast<float2*>(r1 + nc2) = make_float2(acc[mt][nt][2], acc[mt][nt][3]);
            }
        }
    }
}

extern "C" void kernel_launch(void* const* d_in, const int* in_sizes, int n_in,
                              void* d_out, int out_size)
{
    const float* h1   = (const float*)d_in[0];
    const float* cost = (const float*)d_in[1];
    float* out        = (float*)d_out;

    cudaFuncSetAttribute(corr_mma_kernel, cudaFuncAttributeMaxDynamicSharedMemorySize, SMEM_TOTAL);

    dim3 grid(NW / W_TILE, NH, NB);
    corr_mma_kernel<<<grid, THREADS, SMEM_TOTAL>>>(h1, cost, out);
}

// round 8
// speedup vs baseline: 1.3635x; 1.3635x over previous
#include <cuda_runtime.h>
#include <cuda_bf16.h>
#include <cstdint>

#define NB 4
#define NC 128
#define NH 256
#define NW 512
#define ND 64
#define W_TILE 64
#define THREADS 256

// SMEM (bytes): bf16 tiles, rows of 128 elements = 256B (16 chunks of 16B).
// Chunk-XOR swizzle: chunk' = chunk ^ (row & 7)  -> ldmatrix conflict-free.
#define SM_AHI  0                       // A_hi [128m x 128k] bf16 (32KB)
#define SM_ALO  (SM_AHI + 32768)        // A_lo (32KB)
#define SM_BHI  (SM_ALO + 32768)        // B_hi [64n x 128k] bf16 (16KB)
#define SM_BLO  (SM_BHI + 16384)        // B_lo (16KB)
#define SMEM_TOTAL (SM_BLO + 16384)     // 98304 -> 2 CTAs/SM

__device__ __forceinline__ uint32_t smem_u32(const void* p) {
    uint32_t a;
    asm("{ .reg .u64 t; cvta.to.shared.u64 t, %1; cvt.u32.u64 %0, t; }" : "=r"(a) : "l"(p));
    return a;
}
__device__ __forceinline__ uint32_t tile_off(int row, int k) {
    return (uint32_t)(row * 256 + (((k >> 3) ^ (row & 7)) << 4) + (k & 7) * 2);
}
__device__ __forceinline__ void bsplit(float x, uint16_t& hi, uint16_t& lo) {
    __nv_bfloat16 h = __float2bfloat16(x);
    __nv_bfloat16 l = __float2bfloat16(x - __bfloat162float(h));
    hi = *reinterpret_cast<uint16_t*>(&h);
    lo = *reinterpret_cast<uint16_t*>(&l);
}
__device__ __forceinline__ void ldsm4(uint32_t* r, uint32_t addr) {
    asm volatile("ldmatrix.sync.aligned.m8n8.x4.shared.b16 {%0,%1,%2,%3}, [%4];"
                 : "=r"(r[0]), "=r"(r[1]), "=r"(r[2]), "=r"(r[3]) : "r"(addr));
}
__device__ __forceinline__ void mma16816(float* c, const uint32_t* a, const uint32_t* b) {
    asm volatile("mma.sync.aligned.m16n8k16.row.col.f32.bf16.bf16.f32 "
                 "{%0,%1,%2,%3}, {%4,%5,%6,%7}, {%8,%9}, {%0,%1,%2,%3};"
                 : "+f"(c[0]), "+f"(c[1]), "+f"(c[2]), "+f"(c[3])
                 : "r"(a[0]), "r"(a[1]), "r"(a[2]), "r"(a[3]), "r"(b[0]), "r"(b[1]));
}

// Band-pruned mainloop, specialized on the warp's n offset (0 or 32).
// B[w][k] nonzero iff k-w in [0,64). For n8 tile at nb: nonzero k in [nb, nb+70].
template <int NWARP>
__device__ __forceinline__ void mainloop(uint32_t smb, int m_warp,
                                         int a_m, int a_ks, int b_n, int b_ks,
                                         float acc[2][4][4])
{
    #pragma unroll
    for (int ks = 0; ks < 8; ks++) {
        const bool needA = (ks >= NWARP / 16) && (ks <= NWARP / 16 + 5);
        if (!needA) continue;
        uint32_t ahi[2][4], alo[2][4], bhi[2][4], blo[2][4];
        #pragma unroll
        for (int mt = 0; mt < 2; mt++) {
            const int m = m_warp + mt * 16 + a_m;
            const uint32_t off = (uint32_t)(m * 256 + (((ks * 2 + a_ks) ^ (m & 7)) << 4));
            ldsm4(ahi[mt], smb + SM_AHI + off);
            ldsm4(alo[mt], smb + SM_ALO + off);
        }
        #pragma unroll
        for (int p = 0; p < 2; p++) {
            const bool needB = (ks >= NWARP / 16 + p) && (ks <= NWARP / 16 + p + 4);
            if (!needB) continue;
            const int n = NWARP + p * 16 + b_n;
            const uint32_t off = (uint32_t)(n * 256 + (((ks * 2 + b_ks) ^ (n & 7)) << 4));
            ldsm4(bhi[p], smb + SM_BHI + off);
            ldsm4(blo[p], smb + SM_BLO + off);
        }
        #pragma unroll
        for (int mt = 0; mt < 2; mt++) {
            #pragma unroll
            for (int nt = 0; nt < 4; nt++) {
                const int nb = NWARP + nt * 8;
                const bool use = (16 * ks <= nb + 70) && (16 * ks + 15 >= nb);
                if (!use) continue;
                const uint32_t* bh = &bhi[nt >> 1][(nt & 1) * 2];
                const uint32_t* bl = &blo[nt >> 1][(nt & 1) * 2];
                mma16816(acc[mt][nt], ahi[mt], bh);
                mma16816(acc[mt][nt], ahi[mt], bl);
                mma16816(acc[mt][nt], alo[mt], bh);
            }
        }
    }
}

__global__ void __launch_bounds__(THREADS, 2)
corr_mma_kernel(const float* __restrict__ h1,
                const float* __restrict__ cost,
                float* __restrict__ out)
{
    extern __shared__ char smem[];
    const uint32_t smb = smem_u32(smem);
    const int tid  = threadIdx.x;
    const int wid  = tid >> 5;
    const int lane = tid & 31;

    const int wt = blockIdx.x;   // 0..7
    const int hh = blockIdx.y;   // 0..255
    const int bb = blockIdx.z;   // 0..3
    const int w0 = wt * W_TILE;

    // ---- Phase 1a: cost LDG first (DRAM latency hides under A convert) ----
    float4 cv[4];
    int cd[4], cw[4];
    #pragma unroll
    for (int j = 0; j < 4; j++) {
        const int idx = j * THREADS + tid;
        cd[j] = idx >> 4;          // d
        cw[j] = (idx & 15) * 4;    // w base
        cv[j] = *reinterpret_cast<const float4*>(
                    cost + (((size_t)bb * ND + cd[j]) * NH + hh) * NW + w0 + cw[j]);
    }

    // ---- Phase 1b: sparse-zero B. Row w (group g=w/16) is read in k in
    // [16g, 16g+80); the scatter writes k in [w, w+64). Unwritten-but-read
    // stripes are chunks {2g, 2g+1, 2g+8, 2g+9}. 512 16B zero-stores total.
    {
        const uint4 z = make_uint4(0, 0, 0, 0);
        #pragma unroll
        for (int i = 0; i < 2; i++) {
            const int idx  = tid * 2 + i;        // 0..511
            const int tile = idx >> 8;           // 0 = hi, 1 = lo
            const int rr   = idx & 255;
            const int row  = rr >> 2;            // 0..63
            const int cc   = rr & 3;
            const int chunk = 2 * (row >> 4) + (cc & 1) + (cc >> 1) * 8;
            const uint32_t off = tile_off(row, chunk * 8);
            *reinterpret_cast<uint4*>(smem + (tile ? SM_BLO : SM_BHI) + off) = z;
        }
    }

    // ---- Phase 1c: load+split A (R5 coalesced pattern: one float4/thread/iter) ----
    {
        #pragma unroll
        for (int j = 0; j < 16; j++) {
            const int idx = j * THREADS + tid;
            const int row = idx >> 5;          // c
            const int q   = idx & 31;          // float4 within row
            const int gw  = w0 + q * 4;
            float4 v = make_float4(0.f, 0.f, 0.f, 0.f);
            if (gw < NW)
                v = *reinterpret_cast<const float4*>(
                        h1 + (((size_t)bb * NC + row) * NH + hh) * NW + gw);
            uint16_t ha, la, hb2, lb, hc, lc, hd, ld;
            bsplit(v.x, ha, la); bsplit(v.y, hb2, lb);
            bsplit(v.z, hc, lc); bsplit(v.w, hd, ld);
            uint2 hp, lp;
            hp.x = (uint32_t)ha | ((uint32_t)hb2 << 16);
            hp.y = (uint32_t)hc | ((uint32_t)hd << 16);
            lp.x = (uint32_t)la | ((uint32_t)lb << 16);
            lp.y = (uint32_t)lc | ((uint32_t)ld << 16);
            const uint32_t off = tile_off(row, q * 4);
            *reinterpret_cast<uint2*>(smem + SM_AHI + off) = hp;
            *reinterpret_cast<uint2*>(smem + SM_ALO + off) = lp;
        }
    }
    __syncthreads();

    // ---- Phase 2: shear-scatter cost into B: B[w][w+d] = cost[d][w] ----
    {
        #pragma unroll
        for (int j = 0; j < 4; j++) {
            const float x[4] = {cv[j].x, cv[j].y, cv[j].z, cv[j].w};
            #pragma unroll
            for (int e = 0; e < 4; e++) {
                const int w = cw[j] + e;
                const uint32_t off = tile_off(w, w + cd[j]);
                uint16_t hi, lo;
                bsplit(x[e], hi, lo);
                *reinterpret_cast<uint16_t*>(smem + SM_BHI + off) = hi;
                *reinterpret_cast<uint16_t*>(smem + SM_BLO + off) = lo;
            }
        }
    }
    __syncthreads();

    // ---- Phase 3: warp-tile GEMM. Warp = 32m x 32n; band-pruned K ----
    const int m_warp = (wid & 3) * 32;
    const int n_warp = (wid >> 2) * 32;
    const int qd = lane >> 2;
    const int tq = lane & 3;

    const int sub  = lane >> 3;
    const int rid  = lane & 7;
    const int a_m  = (sub & 1) * 8 + rid;
    const int a_ks = (sub >> 1);
    const int b_n  = (sub >> 1) * 8 + rid;
    const int b_ks = (sub & 1);

    float acc[2][4][4];
    #pragma unroll
    for (int mt = 0; mt < 2; mt++)
        #pragma unroll
        for (int nt = 0; nt < 4; nt++)
            #pragma unroll
            for (int e = 0; e < 4; e++) acc[mt][nt][e] = 0.f;

    if (n_warp == 0)
        mainloop<0>(smb, m_warp, a_m, a_ks, b_n, b_ks, acc);
    else
        mainloop<32>(smb, m_warp, a_m, a_ks, b_n, b_ks, acc);

    // ---- Epilogue ----
    {
        #pragma unroll
        for (int mt = 0; mt < 2; mt++) {
            const int m0 = m_warp + mt * 16 + qd;
            float* r0 = out + (((size_t)bb * NC + m0) * NH + hh) * NW + w0 + n_warp;
            float* r1 = out + (((size_t)bb * NC + m0 + 8) * NH + hh) * NW + w0 + n_warp;
            #pragma unroll
            for (int nt = 0; nt < 4; nt++) {
                const int nc2 = nt * 8 + tq * 2;
                *reinterpret_cast<float2*>(r0 + nc2) = make_float2(acc[mt][nt][0], acc[mt][nt][1]);
                *reinterpret_cast<float2*>(r1 + nc2) = make_float2(acc[mt][nt][2], acc[mt][nt][3]);
            }
        }
    }
}

extern "C" void kernel_launch(void* const* d_in, const int* in_sizes, int n_in,
                              void* d_out, int out_size)
{
    const float* h1   = (const float*)d_in[0];
    const float* cost = (const float*)d_in[1];
    float* out        = (float*)d_out;

    cudaFuncSetAttribute(corr_mma_kernel, cudaFuncAttributeMaxDynamicSharedMemorySize, SMEM_TOTAL);

    dim3 grid(NW / W_TILE, NH, NB);
    corr_mma_kernel<<<grid, THREADS, SMEM_TOTAL>>>(h1, cost, out);
}

// round 10
// speedup vs baseline: 1.6224x; 1.1899x over previous
#include <cuda_runtime.h>
#include <cuda_bf16.h>
#include <cstdint>

#define NB 4
#define NC 128
#define NH 256
#define NW 512
#define ND 64
#define W_TILE 64
#define THREADS 256

// SMEM: f32 tiles. Rows of 128 k-elements = 512B = 32 x 16B chunks.
// Chunk swizzle: c' = c ^ ((row&7)<<1)  -> conflict-free frag loads.
#define SM_A 0                          // A [128c x 128k] f32 (64KB)
#define SM_B 65536                      // B [64w x 128k] f32 (32KB)
#define SMEM_TOTAL 98304                // 2 CTAs/SM

__device__ __forceinline__ uint32_t smem_u32(const void* p) {
    uint32_t a;
    asm("{ .reg .u64 t; cvta.to.shared.u64 t, %1; cvt.u32.u64 %0, t; }" : "=r"(a) : "l"(p));
    return a;
}
__device__ __forceinline__ uint32_t f32_off(int row, int k) {
    return (uint32_t)(row * 512 + ((((k >> 2) ^ ((row & 7) << 1)) & 31) << 4) + (k & 3) * 4);
}
// pack two f32 -> bf16x2 (lo half = v.x)
__device__ __forceinline__ uint32_t pack_hi(float2 v) {
    uint32_t r;
    asm("cvt.rn.bf16x2.f32 %0, %1, %2;" : "=r"(r) : "f"(v.y), "f"(v.x));
    return r;
}
// residual: lo bf16x2 = bf16(v - as_float(hi))
__device__ __forceinline__ uint32_t pack_lo(float2 v, uint32_t h) {
    float hx = __uint_as_float(h << 16);
    float hy = __uint_as_float(h & 0xFFFF0000u);
    float2 l = make_float2(v.x - hx, v.y - hy);
    uint32_t r;
    asm("cvt.rn.bf16x2.f32 %0, %1, %2;" : "=r"(r) : "f"(l.y), "f"(l.x));
    return r;
}
__device__ __forceinline__ float2 lds64(uint32_t addr) {
    float2 v;
    asm volatile("ld.shared.v2.f32 {%0,%1}, [%2];" : "=f"(v.x), "=f"(v.y) : "r"(addr));
    return v;
}
__device__ __forceinline__ void cpasync16(uint32_t dst, const void* src, int sz) {
    asm volatile("cp.async.cg.shared.global [%0], [%1], 16, %2;"
                 :: "r"(dst), "l"(src), "r"(sz) : "memory");
}
__device__ __forceinline__ void mma16816(float* c, const uint32_t* a, const uint32_t* b) {
    asm volatile("mma.sync.aligned.m16n8k16.row.col.f32.bf16.bf16.f32 "
                 "{%0,%1,%2,%3}, {%4,%5,%6,%7}, {%8,%9}, {%0,%1,%2,%3};"
                 : "+f"(c[0]), "+f"(c[1]), "+f"(c[2]), "+f"(c[3])
                 : "r"(a[0]), "r"(a[1]), "r"(a[2]), "r"(a[3]), "r"(b[0]), "r"(b[1]));
}

// Band-pruned mainloop with in-register bf16 split.
// B[w][k] nonzero iff k-w in [0,64). For n8 tile at nb: nonzero k in [nb, nb+70].
template <int NWARP>
__device__ __forceinline__ void mainloop(uint32_t smb, int m_warp, int qd, int tq,
                                         float acc[2][4][4])
{
    #pragma unroll
    for (int ks = 0; ks < 8; ks++) {
        const bool needA = (ks >= NWARP / 16) && (ks <= NWARP / 16 + 5);
        if (!needA) continue;

        // A frags (m16n8k16 row-major): regs = (qd,k0),(qd+8,k0),(qd,k0+8),(qd+8,k0+8)
        uint32_t ahi[2][4], alo[2][4];
        #pragma unroll
        for (int mt = 0; mt < 2; mt++) {
            const int rm = m_warp + mt * 16;
            const int k0 = ks * 16 + tq * 2;
            const float2 v00 = lds64(smb + SM_A + f32_off(rm + qd,     k0));
            const float2 v10 = lds64(smb + SM_A + f32_off(rm + qd + 8, k0));
            const float2 v01 = lds64(smb + SM_A + f32_off(rm + qd,     k0 + 8));
            const float2 v11 = lds64(smb + SM_A + f32_off(rm + qd + 8, k0 + 8));
            ahi[mt][0] = pack_hi(v00); alo[mt][0] = pack_lo(v00, ahi[mt][0]);
            ahi[mt][1] = pack_hi(v10); alo[mt][1] = pack_lo(v10, ahi[mt][1]);
            ahi[mt][2] = pack_hi(v01); alo[mt][2] = pack_lo(v01, ahi[mt][2]);
            ahi[mt][3] = pack_hi(v11); alo[mt][3] = pack_lo(v11, ahi[mt][3]);
        }

        // B frags (col-major n8k16): b0 = B[n][k0..k0+1], b1 = B[n][k0+8..+9]
        uint32_t bhi[2][4], blo[2][4];
        #pragma unroll
        for (int p = 0; p < 2; p++) {
            const bool needB = (ks >= NWARP / 16 + p) && (ks <= NWARP / 16 + p + 4);
            if (!needB) continue;
            const int k0 = ks * 16 + tq * 2;
            #pragma unroll
            for (int t = 0; t < 2; t++) {
                const int n = NWARP + p * 16 + t * 8 + qd;
                const float2 u0 = lds64(smb + SM_B + f32_off(n, k0));
                const float2 u1 = lds64(smb + SM_B + f32_off(n, k0 + 8));
                bhi[p][t * 2 + 0] = pack_hi(u0); blo[p][t * 2 + 0] = pack_lo(u0, bhi[p][t * 2 + 0]);
                bhi[p][t * 2 + 1] = pack_hi(u1); blo[p][t * 2 + 1] = pack_lo(u1, bhi[p][t * 2 + 1]);
            }
        }

        #pragma unroll
        for (int mt = 0; mt < 2; mt++) {
            #pragma unroll
            for (int nt = 0; nt < 4; nt++) {
                const int nb = NWARP + nt * 8;
                const bool use = (16 * ks <= nb + 70) && (16 * ks + 15 >= nb);
                if (!use) continue;
                const uint32_t* bh = &bhi[nt >> 1][(nt & 1) * 2];
                const uint32_t* bl = &blo[nt >> 1][(nt & 1) * 2];
                mma16816(acc[mt][nt], ahi[mt], bh);
                mma16816(acc[mt][nt], ahi[mt], bl);
                mma16816(acc[mt][nt], alo[mt], bh);
            }
        }
    }
}

__global__ void __launch_bounds__(THREADS, 2)
corr_mma_kernel(const float* __restrict__ h1,
                const float* __restrict__ cost,
                float* __restrict__ out)
{
    extern __shared__ char smem[];
    const uint32_t smb = smem_u32(smem);
    const int tid  = threadIdx.x;
    const int wid  = tid >> 5;
    const int lane = tid & 31;

    const int wt = blockIdx.x;   // 0..7
    const int hh = blockIdx.y;   // 0..255
    const int bb = blockIdx.z;   // 0..3
    const int w0 = wt * W_TILE;

    // ---- cost LDG first (latency overlaps async setup + zero) ----
    float4 cv[4];
    int cd[4], cw[4];
    #pragma unroll
    for (int j = 0; j < 4; j++) {
        const int idx = j * THREADS + tid;
        cd[j] = idx >> 4;          // d
        cw[j] = (idx & 15) * 4;    // w base
        cv[j] = *reinterpret_cast<const float4*>(
                    cost + (((size_t)bb * ND + cd[j]) * NH + hh) * NW + w0 + cw[j]);
    }

    // ---- A tile via cp.async: 4096 16B chunks, 16 per thread ----
    {
        #pragma unroll
        for (int j = 0; j < 16; j++) {
            const int idx = j * THREADS + tid;
            const int row = idx >> 5;          // c
            const int c4  = idx & 31;          // 16B chunk in row
            const int gw  = w0 + c4 * 4;
            const uint32_t dst = smb + SM_A + (uint32_t)(row * 512 + ((c4 ^ ((row & 7) << 1)) << 4));
            const float* src = h1 + (((size_t)bb * NC + row) * NH + hh) * NW + gw;
            cpasync16(dst, src, gw < NW ? 16 : 0);
        }
        asm volatile("cp.async.commit_group;" ::: "memory");
    }

    // ---- sparse-zero B: row group g reads k in [16g,16g+80); scatter writes
    // [w,w+64). Unwritten stripes = chunks [4g,4g+4) u [4g+16,4g+20). ----
    {
        const uint4 z = make_uint4(0, 0, 0, 0);
        #pragma unroll
        for (int i = 0; i < 2; i++) {
            const int idx = tid * 2 + i;         // 0..511
            const int row = idx >> 3;            // 0..63
            const int cc  = idx & 7;
            const int c   = 4 * (row >> 4) + (cc < 4 ? cc : 12 + cc);
            *reinterpret_cast<uint4*>(smem + SM_B + row * 512 + ((c ^ ((row & 7) << 1)) << 4)) = z;
        }
    }

    // Zero-stripes and scatter writes overlap within 16B chunks (row w scatters
    // k in [w, w+64) which intrudes into [16g, 16g+16)). MUST order them.
    __syncthreads();

    // ---- shear-scatter (f32): B[w][w+d] = cost[d][w] ----
    {
        #pragma unroll
        for (int j = 0; j < 4; j++) {
            const float x[4] = {cv[j].x, cv[j].y, cv[j].z, cv[j].w};
            #pragma unroll
            for (int e = 0; e < 4; e++) {
                const int w = cw[j] + e;
                *reinterpret_cast<float*>(smem + SM_B + f32_off(w, w + cd[j])) = x[e];
            }
        }
    }

    asm volatile("cp.async.wait_group 0;" ::: "memory");
    __syncthreads();

    // ---- warp-tile GEMM: warp = 32m x 32n, band-pruned, in-reg split ----
    const int m_warp = (wid & 3) * 32;
    const int n_warp = (wid >> 2) * 32;
    const int qd = lane >> 2;
    const int tq = lane & 3;

    float acc[2][4][4];
    #pragma unroll
    for (int mt = 0; mt < 2; mt++)
        #pragma unroll
        for (int nt = 0; nt < 4; nt++)
            #pragma unroll
            for (int e = 0; e < 4; e++) acc[mt][nt][e] = 0.f;

    if (n_warp == 0)
        mainloop<0>(smb, m_warp, qd, tq, acc);
    else
        mainloop<32>(smb, m_warp, qd, tq, acc);

    // ---- Epilogue ----
    {
        #pragma unroll
        for (int mt = 0; mt < 2; mt++) {
            const int m0 = m_warp + mt * 16 + qd;
            float* r0 = out + (((size_t)bb * NC + m0) * NH + hh) * NW + w0 + n_warp;
            float* r1 = out + (((size_t)bb * NC + m0 + 8) * NH + hh) * NW + w0 + n_warp;
            #pragma unroll
            for (int nt = 0; nt < 4; nt++) {
                const int nc2 = nt * 8 + tq * 2;
                *reinterpret_cast<float2*>(r0 + nc2) = make_float2(acc[mt][nt][0], acc[mt][nt][1]);
                *reinterpret_cast<float2*>(r1 + nc2) = make_float2(acc[mt][nt][2], acc[mt][nt][3]);
            }
        }
    }
}

extern "C" void kernel_launch(void* const* d_in, const int* in_sizes, int n_in,
                              void* d_out, int out_size)
{
    const float* h1   = (const float*)d_in[0];
    const float* cost = (const float*)d_in[1];
    float* out        = (float*)d_out;

    cudaFuncSetAttribute(corr_mma_kernel, cudaFuncAttributeMaxDynamicSharedMemorySize, SMEM_TOTAL);

    dim3 grid(NW / W_TILE, NH, NB);
    corr_mma_kernel<<<grid, THREADS, SMEM_TOTAL>>>(h1, cost, out);
}

// round 11
// speedup vs baseline: 1.6631x; 1.0251x over previous
#include <cuda_runtime.h>
#include <cuda_bf16.h>
#include <cstdint>

#define NB 4
#define NC 128
#define NH 256
#define NW 512
#define ND 64
#define W_TILE 64
#define THREADS 512

// SMEM: A as f32 (rows of 128 k = 512B, chunk swizzle c^( (row&7)<<1 )),
//       B pre-split bf16 hi/lo (rows of 128 k = 256B, chunk swizzle c^(row&7)).
#define SM_A   0                        // A [128c x 128k] f32 (64KB)
#define SM_BHI 65536                    // B_hi [64w x 128k] bf16 (16KB)
#define SM_BLO 81920                    // B_lo (16KB)
#define SMEM_TOTAL 98304                // 2 CTAs/SM

__device__ __forceinline__ uint32_t smem_u32(const void* p) {
    uint32_t a;
    asm("{ .reg .u64 t; cvta.to.shared.u64 t, %1; cvt.u32.u64 %0, t; }" : "=r"(a) : "l"(p));
    return a;
}
// f32 A tile offset
__device__ __forceinline__ uint32_t f32_off(int row, int k) {
    return (uint32_t)(row * 512 + ((((k >> 2) ^ ((row & 7) << 1)) & 31) << 4) + (k & 3) * 4);
}
// bf16 B tile offset (R5 layout)
__device__ __forceinline__ uint32_t b16_off(int row, int k) {
    return (uint32_t)(row * 256 + (((k >> 3) ^ (row & 7)) << 4) + (k & 7) * 2);
}
__device__ __forceinline__ void bsplit(float x, uint16_t& hi, uint16_t& lo) {
    __nv_bfloat16 h = __float2bfloat16(x);
    __nv_bfloat16 l = __float2bfloat16(x - __bfloat162float(h));
    hi = *reinterpret_cast<uint16_t*>(&h);
    lo = *reinterpret_cast<uint16_t*>(&l);
}
__device__ __forceinline__ uint32_t pack_hi(float2 v) {
    uint32_t r;
    asm("cvt.rn.bf16x2.f32 %0, %1, %2;" : "=r"(r) : "f"(v.y), "f"(v.x));
    return r;
}
__device__ __forceinline__ uint32_t pack_lo(float2 v, uint32_t h) {
    float hx = __uint_as_float(h << 16);
    float hy = __uint_as_float(h & 0xFFFF0000u);
    float2 l = make_float2(v.x - hx, v.y - hy);
    uint32_t r;
    asm("cvt.rn.bf16x2.f32 %0, %1, %2;" : "=r"(r) : "f"(l.y), "f"(l.x));
    return r;
}
__device__ __forceinline__ float2 lds64(uint32_t addr) {
    float2 v;
    asm volatile("ld.shared.v2.f32 {%0,%1}, [%2];" : "=f"(v.x), "=f"(v.y) : "r"(addr));
    return v;
}
__device__ __forceinline__ void ldsm4(uint32_t* r, uint32_t addr) {
    asm volatile("ldmatrix.sync.aligned.m8n8.x4.shared.b16 {%0,%1,%2,%3}, [%4];"
                 : "=r"(r[0]), "=r"(r[1]), "=r"(r[2]), "=r"(r[3]) : "r"(addr));
}
__device__ __forceinline__ void cpasync16(uint32_t dst, const void* src, int sz) {
    asm volatile("cp.async.cg.shared.global [%0], [%1], 16, %2;"
                 :: "r"(dst), "l"(src), "r"(sz) : "memory");
}
__device__ __forceinline__ void mma16816(float* c, const uint32_t* a, const uint32_t* b) {
    asm volatile("mma.sync.aligned.m16n8k16.row.col.f32.bf16.bf16.f32 "
                 "{%0,%1,%2,%3}, {%4,%5,%6,%7}, {%8,%9}, {%0,%1,%2,%3};"
                 : "+f"(c[0]), "+f"(c[1]), "+f"(c[2]), "+f"(c[3])
                 : "r"(a[0]), "r"(a[1]), "r"(a[2]), "r"(a[3]), "r"(b[0]), "r"(b[1]));
}

// Band-pruned mainloop: warp = 16m x 32n. A f32 in-reg split; B bf16 via ldmatrix.
// B[w][k] nonzero iff k-w in [0,64); n8 tile at nb needs k in [nb, nb+70].
template <int NWARP>
__device__ __forceinline__ void mainloop(uint32_t smb, int m_warp, int qd, int tq,
                                         int b_n, int b_ks, float acc[4][4])
{
    #pragma unroll
    for (int ks = 0; ks < 8; ks++) {
        const bool needA = (ks >= NWARP / 16) && (ks <= NWARP / 16 + 5);
        if (!needA) continue;

        // A frag (m16n8k16 row-major): (qd,k0),(qd+8,k0),(qd,k0+8),(qd+8,k0+8)
        uint32_t ahi[4], alo[4];
        {
            const int k0 = ks * 16 + tq * 2;
            const float2 v00 = lds64(smb + SM_A + f32_off(m_warp + qd,     k0));
            const float2 v10 = lds64(smb + SM_A + f32_off(m_warp + qd + 8, k0));
            const float2 v01 = lds64(smb + SM_A + f32_off(m_warp + qd,     k0 + 8));
            const float2 v11 = lds64(smb + SM_A + f32_off(m_warp + qd + 8, k0 + 8));
            ahi[0] = pack_hi(v00); alo[0] = pack_lo(v00, ahi[0]);
            ahi[1] = pack_hi(v10); alo[1] = pack_lo(v10, ahi[1]);
            ahi[2] = pack_hi(v01); alo[2] = pack_lo(v01, ahi[2]);
            ahi[3] = pack_hi(v11); alo[3] = pack_lo(v11, ahi[3]);
        }

        // B frags via ldmatrix (R5-verified addressing)
        uint32_t bhi[2][4], blo[2][4];
        #pragma unroll
        for (int p = 0; p < 2; p++) {
            const bool needB = (ks >= NWARP / 16 + p) && (ks <= NWARP / 16 + p + 4);
            if (!needB) continue;
            const int n = NWARP + p * 16 + b_n;
            const uint32_t off = (uint32_t)(n * 256 + (((ks * 2 + b_ks) ^ (n & 7)) << 4));
            ldsm4(bhi[p], smb + SM_BHI + off);
            ldsm4(blo[p], smb + SM_BLO + off);
        }

        #pragma unroll
        for (int nt = 0; nt < 4; nt++) {
            const int nb = NWARP + nt * 8;
            const bool use = (16 * ks <= nb + 70) && (16 * ks + 15 >= nb);
            if (!use) continue;
            const uint32_t* bh = &bhi[nt >> 1][(nt & 1) * 2];
            const uint32_t* bl = &blo[nt >> 1][(nt & 1) * 2];
            mma16816(acc[nt], ahi, bh);
            mma16816(acc[nt], ahi, bl);
            mma16816(acc[nt], alo, bh);
        }
    }
}

__global__ void __launch_bounds__(THREADS, 2)
corr_mma_kernel(const float* __restrict__ h1,
                const float* __restrict__ cost,
                float* __restrict__ out)
{
    extern __shared__ char smem[];
    const uint32_t smb = smem_u32(smem);
    const int tid  = threadIdx.x;
    const int wid  = tid >> 5;
    const int lane = tid & 31;

    const int wt = blockIdx.x;   // 0..7
    const int hh = blockIdx.y;   // 0..255
    const int bb = blockIdx.z;   // 0..3
    const int w0 = wt * W_TILE;

    // ---- cost LDG first: 8 floats/thread ----
    float4 cv[2];
    int cd[2], cw[2];
    #pragma unroll
    for (int j = 0; j < 2; j++) {
        const int idx = j * THREADS + tid;   // 0..1023
        cd[j] = idx >> 4;          // d
        cw[j] = (idx & 15) * 4;    // w base
        cv[j] = *reinterpret_cast<const float4*>(
                    cost + (((size_t)bb * ND + cd[j]) * NH + hh) * NW + w0 + cw[j]);
    }

    // ---- A tile via cp.async: 4096 chunks, 8/thread ----
    {
        #pragma unroll
        for (int j = 0; j < 8; j++) {
            const int idx = j * THREADS + tid;
            const int row = idx >> 5;
            const int c4  = idx & 31;
            const int gw  = w0 + c4 * 4;
            const uint32_t dst = smb + SM_A + (uint32_t)(row * 512 + ((c4 ^ ((row & 7) << 1)) << 4));
            const float* src = h1 + (((size_t)bb * NC + row) * NH + hh) * NW + gw;
            cpasync16(dst, src, gw < NW ? 16 : 0);
        }
        asm volatile("cp.async.commit_group;" ::: "memory");
    }

    // ---- sparse-zero B stripes (bf16 tiles): 512 chunk-zeros, 1/thread ----
    {
        const uint4 z = make_uint4(0, 0, 0, 0);
        const int idx  = tid;                // 0..511
        const int tile = idx >> 8;           // 0 = hi, 1 = lo
        const int rr   = idx & 255;
        const int row  = rr >> 2;            // 0..63
        const int cc   = rr & 3;
        const int chunk = 2 * (row >> 4) + (cc & 1) + (cc >> 1) * 8;
        const uint32_t off = b16_off(row, chunk * 8);
        *reinterpret_cast<uint4*>(smem + (tile ? SM_BLO : SM_BHI) + off) = z;
    }

    // zero-stripes and scatter overlap within chunks -> must order (R9 lesson)
    __syncthreads();

    // ---- shear-scatter cost -> B hi/lo: B[w][w+d] = cost[d][w] ----
    {
        #pragma unroll
        for (int j = 0; j < 2; j++) {
            const float x[4] = {cv[j].x, cv[j].y, cv[j].z, cv[j].w};
            #pragma unroll
            for (int e = 0; e < 4; e++) {
                const int w = cw[j] + e;
                const uint32_t off = b16_off(w, w + cd[j]);
                uint16_t hi, lo;
                bsplit(x[e], hi, lo);
                *reinterpret_cast<uint16_t*>(smem + SM_BHI + off) = hi;
                *reinterpret_cast<uint16_t*>(smem + SM_BLO + off) = lo;
            }
        }
    }

    asm volatile("cp.async.wait_group 0;" ::: "memory");
    __syncthreads();

    // ---- warp-tile GEMM: 16 warps of 16m x 32n ----
    const int m_warp = (wid & 7) * 16;
    const int n_warp = (wid >> 3) * 32;
    const int qd = lane >> 2;
    const int tq = lane & 3;

    const int sub  = lane >> 3;
    const int rid  = lane & 7;
    const int b_n  = (sub >> 1) * 8 + rid;
    const int b_ks = (sub & 1);

    float acc[4][4];
    #pragma unroll
    for (int nt = 0; nt < 4; nt++)
        #pragma unroll
        for (int e = 0; e < 4; e++) acc[nt][e] = 0.f;

    if (n_warp == 0)
        mainloop<0>(smb, m_warp, qd, tq, b_n, b_ks, acc);
    else
        mainloop<32>(smb, m_warp, qd, tq, b_n, b_ks, acc);

    // ---- Epilogue ----
    {
        const int m0 = m_warp + qd;
        float* r0 = out + (((size_t)bb * NC + m0) * NH + hh) * NW + w0 + n_warp;
        float* r1 = out + (((size_t)bb * NC + m0 + 8) * NH + hh) * NW + w0 + n_warp;
        #pragma unroll
        for (int nt = 0; nt < 4; nt++) {
            const int nc2 = nt * 8 + tq * 2;
            *reinterpret_cast<float2*>(r0 + nc2) = make_float2(acc[nt][0], acc[nt][1]);
            *reinterpret_cast<float2*>(r1 + nc2) = make_float2(acc[nt][2], acc[nt][3]);
        }
    }
}

extern "C" void kernel_launch(void* const* d_in, const int* in_sizes, int n_in,
                              void* d_out, int out_size)
{
    const float* h1   = (const float*)d_in[0];
    const float* cost = (const float*)d_in[1];
    float* out        = (float*)d_out;

    cudaFuncSetAttribute(corr_mma_kernel, cudaFuncAttributeMaxDynamicSharedMemorySize, SMEM_TOTAL);

    dim3 grid(NW / W_TILE, NH, NB);
    corr_mma_kernel<<<grid, THREADS, SMEM_TOTAL>>>(h1, cost, out);
}